// round 9
// baseline (speedup 1.0000x reference)
#include <cuda_runtime.h>
#include <cuda_fp16.h>
#include <cstdint>

// ============================================================================
// LSTMCell on GB300 via mma.sync (HMMA) — tcgen05 unavailable (compute_103 PTX).
// gates[B,512] = [x|h] @ Wcat^T, fp16 operands / fp32 accum, fused epilogue.
//
// R8 -> R9: M=256 per CTA, 4 m-tiles per warp, 1 CTA/SM (acc=128 regs).
// B-LDS per output halves; producer writes whole 16B fragment lanes with
// STS.128 (conflict-free via addr ^ 64*(ks&1); consumer uses 2 precomputed
// bases). Stage = 2 ks, double-buffered, 8 barriers / 256-row tile.
// ============================================================================

// Weights pre-packed in mma-fragment-ready layout with k-permutation pi:
//   within each 16-wide k-chunk: frag j=0 holds k pairs (4l,4l+1), j=1 (4l+2,4l+3)
// addr = ks*4096 + ntp*512 + lane*16 + e*8 + j*4,  ntp = q*2 + g-half
__device__ __align__(16) unsigned char g_wb[4][65536];

__device__ __forceinline__ uint32_t smem_u32(const void* p) {
    uint32_t a;
    asm("{ .reg .u64 t; cvta.to.shared.u64 t, %1; cvt.u32.u64 %0, t; }"
        : "=r"(a) : "l"(p));
    return a;
}

__device__ __forceinline__ float fast_sigmoid(float x) {
    float e, r;
    asm("ex2.approx.f32 %0, %1;" : "=f"(e) : "f"(-1.4426950408889634f * x));
    asm("rcp.approx.f32 %0, %1;" : "=f"(r) : "f"(1.0f + e));
    return r;
}
__device__ __forceinline__ float fast_tanh(float x) {
    float e, r;
    asm("ex2.approx.f32 %0, %1;" : "=f"(e) : "f"(2.8853900817779268f * x));
    asm("rcp.approx.f32 %0, %1;" : "=f"(r) : "f"(e + 1.0f));
    return 1.0f - 2.0f * r;   // handles +-inf correctly -> +-1
}

__device__ __forceinline__ uint32_t cvt_h2(float lo, float hi) {
    uint32_t r;
    asm("cvt.rn.f16x2.f32 %0, %1, %2;" : "=r"(r) : "f"(hi), "f"(lo));
    return r;
}

__device__ __forceinline__ void mma16816(float* d, const uint32_t* a,
                                         uint32_t b0, uint32_t b1) {
    asm volatile(
        "mma.sync.aligned.m16n8k16.row.col.f32.f16.f16.f32 "
        "{%0,%1,%2,%3}, {%4,%5,%6,%7}, {%8,%9}, {%0,%1,%2,%3};\n"
        : "+f"(d[0]), "+f"(d[1]), "+f"(d[2]), "+f"(d[3])
        : "r"(a[0]), "r"(a[1]), "r"(a[2]), "r"(a[3]), "r"(b0), "r"(b1));
}

__device__ __forceinline__ void lds128(uint32_t* r, uint32_t addr) {
    asm volatile("ld.shared.v4.b32 {%0,%1,%2,%3}, [%4];\n"
                 : "=r"(r[0]), "=r"(r[1]), "=r"(r[2]), "=r"(r[3]) : "r"(addr));
}
__device__ __forceinline__ void sts128(uint32_t addr, uint32_t a, uint32_t b,
                                       uint32_t c, uint32_t d) {
    asm volatile("st.shared.v4.b32 [%0], {%1,%2,%3,%4};\n"
                 :: "r"(addr), "r"(a), "r"(b), "r"(c), "r"(d));
}

// ---------------- SMEM layout (dynamic) ----------------
// [0, 65536)        : W fragments
// [65536, 98304)    : A ring, 2 slots x 16KB
//                     slot: [ksIn(2)x8192][mtile(16)x512][fraglane(32)x16B ^64*ksIn]
// [98304, 98816)    : bias bs[4][32]
static constexpr int SMEM_W  = 0;
static constexpr int SMEM_A  = 65536;
static constexpr int SMEM_BS = 98304;
static constexpr int SMEM_TOTAL = SMEM_BS + 512;

// ============================================================================
// Kernel 1: pack weights fp32 -> fp16 B-fragment layout (with k-permutation).
// ============================================================================
__global__ void wconv_kernel(
    const float* __restrict__ Wii, const float* __restrict__ Whi,
    const float* __restrict__ Wif, const float* __restrict__ Whf,
    const float* __restrict__ Wig, const float* __restrict__ Whg,
    const float* __restrict__ Wio, const float* __restrict__ Who)
{
    int idx = blockIdx.x * 256 + threadIdx.x;   // 0..65535 (pairs)
    int gcol = idx >> 7;        // 0..511
    int kp   = idx & 127;       // pair index, k = 2*kp
    int k    = kp * 2;

    int q    = gcol >> 7;
    int hcol = gcol & 127;
    int qh   = hcol >> 5;
    int hc   = hcol & 31;

    int t    = hc >> 3;                 // 8-col group within 32
    int ntp  = q * 2 + (t >> 1);
    int e    = t & 1;
    int l    = (k >> 2) & 3;
    int j    = (k >> 1) & 1;
    int lane = (hc & 7) * 4 + l;
    int ks   = k >> 4;

    const float* Wx;
    const float* Wh;
    switch (q) {
        case 0:  Wx = Wii; Wh = Whi; break;
        case 1:  Wx = Wif; Wh = Whf; break;
        case 2:  Wx = Wig; Wh = Whg; break;
        default: Wx = Wio; Wh = Who; break;
    }
    float2 v;
    if (k < 128) v = ((const float2*)(Wx + hcol * 128))[kp];
    else         v = ((const float2*)(Wh + hcol * 128))[kp - 64];

    __half2 hv = __floats2half2_rn(v.x, v.y);
    *(uint32_t*)&g_wb[qh][(((ks * 8 + ntp) * 32 + lane) * 16) + e * 8 + j * 4] =
        *(uint32_t*)&hv;
}

// ============================================================================
// Kernel 2: persistent GEMM + LSTM epilogue. grid=148x256, 1 CTA/SM.
// blk&3 = qh (hcol quarter); blk>>2 (0..36) strides batch tiles of 256 rows.
// Warp w: mgroup = w&3 (mtiles 4*mgroup..+3), g = w>>2 (ntp half).
// ============================================================================
__global__ void __launch_bounds__(256, 1)
lstm_main_kernel(
    const float* __restrict__ x, const float* __restrict__ h_t,
    const float* __restrict__ c_t,
    const float* __restrict__ b_i, const float* __restrict__ b_f,
    const float* __restrict__ b_g, const float* __restrict__ b_o,
    float* __restrict__ out, int batch, int mt_total)
{
    extern __shared__ char smem[];
    const uint32_t sb = smem_u32(smem);
    const uint32_t sW = sb + SMEM_W;
    const uint32_t sA = sb + SMEM_A;
    float* bs = (float*)(smem + SMEM_BS);

    const int tid  = threadIdx.x;
    const int wid  = tid >> 5;
    const int lane = tid & 31;
    const int qh   = blockIdx.x & 3;
    const int cta  = blockIdx.x >> 2;          // 0..36
    const int mt_stride = gridDim.x >> 2;      // 37

    const int mgroup = wid & 3;
    const int g      = wid >> 2;

    // ---- load W fragments (once) via cp.async ----
    {
        const char* src = (const char*)&g_wb[qh][0] + tid * 16;
        uint32_t dst = sW + tid * 16;
        #pragma unroll
        for (int i = 0; i < 16; i++) {
            asm volatile("cp.async.ca.shared.global [%0], [%1], 16;\n"
                         :: "r"(dst + i * 4096), "l"(src + i * 4096));
        }
        asm volatile("cp.async.commit_group;\n" ::: "memory");
    }
    // ---- biases for this quarter: bs[q][hc] ----
    if (tid < 128) {
        int q  = tid >> 5;
        int hc = tid & 31;
        const float* bp = (q == 0) ? b_i : (q == 1) ? b_f : (q == 2) ? b_g : b_o;
        bs[tid] = bp[qh * 32 + hc];
    }
    asm volatile("cp.async.wait_group 0;\n" ::: "memory");
    __syncthreads();

    // ---- producer geometry ----
    // tid = w*32 + rp*8 + colq ; w2 = w>>1 picks m-tile within i-group,
    // rows (row_lo, row_lo+8) of mtile(i) = 4i + w2, row_lo8 = (w&1)*4 + rp.
    const int colq  = tid & 7;                 // 8-col group within 32-col stage
    const int rp    = (tid >> 3) & 3;
    const int w2    = wid >> 1;
    const int rlo8  = (wid & 1) * 4 + rp;      // 0..7
    const int ksInP = colq >> 2;               // producer ks within stage
    const int lq    = colq & 3;
    const int flP   = rlo8 * 4 + lq;           // fragment lane 0..31
    // STS base for slot 0, i = 0 (mtile = w2); per i add 2048; slot1 +16384.
    const uint32_t stsBase = sA + (uint32_t)(ksInP * 8192 + w2 * 512)
                           + (uint32_t)((flP * 16) ^ (ksInP * 64));
    // per-thread gmem offset within a stage base (floats):
    const int thOff = (w2 * 16 + rlo8) * 128 + colq * 4;

    // ---- consumer geometry ----
    // A fragment (mtile, ks): lane reads 16B at (lane*16) ^ (64*(ks&1)).
    const uint32_t aEven = (uint32_t)(lane * 16);
    const uint32_t aOdd  = aEven ^ 64u;
    const uint32_t bLane = sW + (uint32_t)(g * 512 + lane * 16);
    const size_t cbase = (size_t)batch * 128;

    // ---- persistent tile loop ----
    for (int mt = cta; mt < mt_total; mt += mt_stride) {

        float acc[4][4][2][4];                 // [mtile][gate][e][frag]
        #pragma unroll
        for (int a0 = 0; a0 < 4; a0++)
            #pragma unroll
            for (int a1 = 0; a1 < 4; a1++)
                #pragma unroll
                for (int a2 = 0; a2 < 2; a2++)
                    #pragma unroll
                    for (int a3 = 0; a3 < 4; a3++)
                        acc[a0][a1][a2][a3] = 0.0f;

        const size_t tilebase = (size_t)(mt * 256) * 128 + thOff;
        const float* xT = x   + tilebase;
        const float* hT = h_t + tilebase;

        float4 G[8];                           // staging: 4 (i) x (lo,hi)

        // ---- prologue: stage 0 -> slot 0 ----
        #pragma unroll
        for (int i = 0; i < 4; i++) {
            G[2 * i]     = __ldg((const float4*)(xT + i * 8192));
            G[2 * i + 1] = __ldg((const float4*)(xT + i * 8192 + 1024));
        }
        #pragma unroll
        for (int i = 0; i < 4; i++) {
            uint32_t w0 = cvt_h2(G[2 * i].x,     G[2 * i].y);
            uint32_t w1 = cvt_h2(G[2 * i + 1].x, G[2 * i + 1].y);
            uint32_t w2r = cvt_h2(G[2 * i].z,     G[2 * i].w);
            uint32_t w3 = cvt_h2(G[2 * i + 1].z, G[2 * i + 1].w);
            sts128(stsBase + (uint32_t)(i * 2048), w0, w1, w2r, w3);
        }
        __syncthreads();

        // ---- stage loop: stage = 2 ks ----
        #pragma unroll
        for (int s = 0; s < 8; s++) {
            // prefetch stage s+1 into G
            if (s < 7) {
                const float* p = ((s + 1) < 4 ? xT : hT) + ((s + 1) & 3) * 32;
                #pragma unroll
                for (int i = 0; i < 4; i++) {
                    G[2 * i]     = __ldg((const float4*)(p + i * 8192));
                    G[2 * i + 1] = __ldg((const float4*)(p + i * 8192 + 1024));
                }
            }

            // consume stage s from slot s&1
            {
                const uint32_t slotBase = sA + (uint32_t)((s & 1) * 16384);
                #pragma unroll
                for (int ki = 0; ki < 2; ki++) {
                    const int ks = s * 2 + ki;
                    const uint32_t aBase = slotBase + (uint32_t)(ki * 8192)
                                         + (uint32_t)(mgroup * 2048)
                                         + (ki ? aOdd : aEven);
                    uint32_t A[4][4];
                    #pragma unroll
                    for (int m = 0; m < 4; m++)
                        lds128(A[m], aBase + (uint32_t)(m * 512));
                    const uint32_t bb = bLane + (uint32_t)(ks * 4096);
                    #pragma unroll
                    for (int q = 0; q < 4; q++) {
                        uint32_t B[4];
                        lds128(B, bb + (uint32_t)(q * 1024));
                        #pragma unroll
                        for (int m = 0; m < 4; m++) {
                            mma16816(acc[m][q][0], A[m], B[0], B[1]);
                            mma16816(acc[m][q][1], A[m], B[2], B[3]);
                        }
                    }
                }
            }

            // store stage s+1 into slot (s+1)&1
            if (s < 7) {
                const uint32_t ds = stsBase + (uint32_t)(((s + 1) & 1) * 16384);
                #pragma unroll
                for (int i = 0; i < 4; i++) {
                    uint32_t w0 = cvt_h2(G[2 * i].x,     G[2 * i].y);
                    uint32_t w1 = cvt_h2(G[2 * i + 1].x, G[2 * i + 1].y);
                    uint32_t w2r = cvt_h2(G[2 * i].z,     G[2 * i].w);
                    uint32_t w3 = cvt_h2(G[2 * i + 1].z, G[2 * i + 1].w);
                    sts128(ds + (uint32_t)(i * 2048), w0, w1, w2r, w3);
                }
                __syncthreads();
            }
        }
        // slot0's next write (next tile prologue) is ordered after its last
        // consumers (stage 6) by the barrier at end of stage 6; slot1 (stage 7)
        // consumers finish before the next prologue's barrier.

        // ---- epilogue ----
        #pragma unroll
        for (int m = 0; m < 4; m++) {
            const int rr0 = mt * 256 + (mgroup * 4 + m) * 16 + (lane >> 2);
            #pragma unroll
            for (int e = 0; e < 2; e++) {
                const int hc32 = (((g << 1) + e) << 3) + ((lane & 3) << 1);
                const int hcol = (qh << 5) + hc32;
                const float bi0 = bs[hc32],      bi1 = bs[hc32 + 1];
                const float bf0 = bs[32 + hc32], bf1 = bs[32 + hc32 + 1];
                const float bg0 = bs[64 + hc32], bg1 = bs[64 + hc32 + 1];
                const float bo0 = bs[96 + hc32], bo1 = bs[96 + hc32 + 1];
                #pragma unroll
                for (int rh = 0; rh < 2; rh++) {
                    const int row = rr0 + rh * 8;
                    const float2 cv =
                        __ldg((const float2*)(c_t + (size_t)row * 128 + hcol));

                    float ia0 = acc[m][0][e][rh * 2 + 0] + bi0;
                    float ia1 = acc[m][0][e][rh * 2 + 1] + bi1;
                    float fa0 = acc[m][1][e][rh * 2 + 0] + bf0;
                    float fa1 = acc[m][1][e][rh * 2 + 1] + bf1;
                    float ga0 = acc[m][2][e][rh * 2 + 0] + bg0;
                    float ga1 = acc[m][2][e][rh * 2 + 1] + bg1;
                    float oa0 = acc[m][3][e][rh * 2 + 0] + bo0;
                    float oa1 = acc[m][3][e][rh * 2 + 1] + bo1;

                    float it0 = fast_sigmoid(ia0), it1 = fast_sigmoid(ia1);
                    float ft0 = fast_sigmoid(fa0), ft1 = fast_sigmoid(fa1);
                    float gt0 = fast_tanh(ga0),    gt1 = fast_tanh(ga1);
                    float ot0 = fast_sigmoid(oa0), ot1 = fast_sigmoid(oa1);

                    float cn0 = ft0 * cv.x + it0 * gt0;
                    float cn1 = ft1 * cv.y + it1 * gt1;
                    float hn0 = ot0 * fast_tanh(cn0);
                    float hn1 = ot1 * fast_tanh(cn1);

                    float2 ho = make_float2(hn0, hn1);
                    float2 co = make_float2(cn0, cn1);
                    *(float2*)(out + (size_t)row * 128 + hcol) = ho;
                    *(float2*)(out + cbase + (size_t)row * 128 + hcol) = co;
                }
            }
        }
    }
}

// ============================================================================
// Host launch
// ============================================================================
extern "C" void kernel_launch(void* const* d_in, const int* in_sizes, int n_in,
                              void* d_out, int out_size)
{
    (void)n_in; (void)out_size;
    const float* x   = (const float*)d_in[0];
    const float* h_t = (const float*)d_in[1];
    const float* c_t = (const float*)d_in[2];
    const float* Wii = (const float*)d_in[3];
    const float* Whi = (const float*)d_in[4];
    const float* b_i = (const float*)d_in[5];
    const float* Wif = (const float*)d_in[6];
    const float* Whf = (const float*)d_in[7];
    const float* b_f = (const float*)d_in[8];
    const float* Wig = (const float*)d_in[9];
    const float* Whg = (const float*)d_in[10];
    const float* b_g = (const float*)d_in[11];
    const float* Wio = (const float*)d_in[12];
    const float* Who = (const float*)d_in[13];
    const float* b_o = (const float*)d_in[14];

    const int batch    = in_sizes[0] / 128;
    const int mt_total = batch / 256;

    wconv_kernel<<<256, 256>>>(Wii, Whi, Wif, Whf, Wig, Whg, Wio, Who);

    static bool attr_set = false;
    if (!attr_set) {
        cudaFuncSetAttribute(lstm_main_kernel,
                             cudaFuncAttributeMaxDynamicSharedMemorySize,
                             SMEM_TOTAL);
        attr_set = true;
    }
    lstm_main_kernel<<<148, 256, SMEM_TOTAL>>>(
        x, h_t, c_t, b_i, b_f, b_g, b_o, (float*)d_out, batch, mt_total);
}